// round 14
// baseline (speedup 1.0000x reference)
#include <cuda_runtime.h>
#include <cuda_fp16.h>

#define NEDGES 3200000
#define NNODES 100000

// edge_stats launch geometry (compile-time so the loop is counted/predicate-free)
#define ES_BLOCKS 2000
#define ES_THREADS 256
#define QSTRIDE ((ES_BLOCKS * ES_THREADS) / 4)   // 128000 quads
#define ES_ITERS (NEDGES / QSTRIDE)              // 25 exact

struct __align__(8) h4 { __half2 a, b; };                   // 4 halves = 8 B

// Scratch (static device allocation; no cudaMalloc anywhere)
static __device__ __align__(256) h4 g_h1[NNODES * 4];       // fp16 x@W1^T + bias (6.4 MB)
static __device__ __align__(256) h4 g_h2[NNODES * 4];       // fp16 x@W2^T        (6.4 MB)
static __device__ __align__(256) __half g_e[NEDGES * 16];   // fp16 pre-BN e (102.4 MB)
static __device__ float g_accum[32];                        // sum[16], sumsq[16]
static __device__ __align__(64) float g_scale[16];
static __device__ __align__(64) float g_shift[16];

// ============================================================================
// Kernel 1: per-node precompute h1 = fp16(x@W1^T + (b0+b1+b2)), h2 = fp16(x@W2^T).
// Also zeroes the stat accumulators (stream-ordered before edge_stats).
// ============================================================================
__global__ void node_prep(const float* __restrict__ x,
                          const float* __restrict__ W1,
                          const float* __restrict__ W2,
                          const float* __restrict__ b0,
                          const float* __restrict__ b1,
                          const float* __restrict__ b2) {
    __shared__ float W1t[256], W2t[256], bt[16];
    int tid = threadIdx.x;
    {
        int j = tid >> 4, k = tid & 15;          // W[j][k] at flat idx tid
        W1t[k * 16 + j] = W1[tid];               // transpose to [k][j]
        W2t[k * 16 + j] = W2[tid];
    }
    if (tid < 16) bt[tid] = b0[tid] + b1[tid] + b2[tid];
    __syncthreads();

    int n = blockIdx.x * blockDim.x + tid;
    if (n < NNODES) {
        const float4* xv = (const float4*)x + n * 4;
        float4 x0 = xv[0], x1 = xv[1], x2 = xv[2], x3 = xv[3];
        float xr[16] = {x0.x, x0.y, x0.z, x0.w, x1.x, x1.y, x1.z, x1.w,
                        x2.x, x2.y, x2.z, x2.w, x3.x, x3.y, x3.z, x3.w};
        float a1[16], a2[16];
        #pragma unroll
        for (int j = 0; j < 16; j++) { a1[j] = bt[j]; a2[j] = 0.f; }
        #pragma unroll
        for (int k = 0; k < 16; k++) {
            float xk = xr[k];
            #pragma unroll
            for (int j = 0; j < 16; j++) {
                a1[j] = fmaf(xk, W1t[k * 16 + j], a1[j]);
                a2[j] = fmaf(xk, W2t[k * 16 + j], a2[j]);
            }
        }
        #pragma unroll
        for (int qq = 0; qq < 4; qq++) {
            h4 v1, v2;
            v1.a = __floats2half2_rn(a1[4 * qq + 0], a1[4 * qq + 1]);
            v1.b = __floats2half2_rn(a1[4 * qq + 2], a1[4 * qq + 3]);
            v2.a = __floats2half2_rn(a2[4 * qq + 0], a2[4 * qq + 1]);
            v2.b = __floats2half2_rn(a2[4 * qq + 2], a2[4 * qq + 3]);
            g_h1[n * 4 + qq] = v1;
            g_h2[n * 4 + qq] = v2;
        }
    }
    if (blockIdx.x == 0 && tid < 32) g_accum[tid] = 0.f;
}

// ============================================================================
// Kernel 2: pass 1 — quad layout (thread q owns features 4q..4q+3).
// 3-stage software pipeline: index loads 2 iterations ahead, data loads
// (ea slice + both fp16 node gathers, 1 sector each) 1 iteration ahead.
// Counted loop (25 iters exactly). W0 rows register-resident.
// ============================================================================
__global__ void __launch_bounds__(ES_THREADS, 2) edge_stats(const float* __restrict__ ea,
                                                            const int* __restrict__ ei,
                                                            const float* __restrict__ W0) {
    __shared__ float red[8][32];
    int tid = threadIdx.x;
    int q = tid & 3;
    int lane = tid & 31;
    int qbase = lane & 28;

    // w[i][g] = W0[4q+i][4g..4g+3]  (loop-invariant, register-resident)
    float4 w[4][4];
    #pragma unroll
    for (int i = 0; i < 4; i++)
        #pragma unroll
        for (int g = 0; g < 4; g++)
            w[i][g] = __ldg(&((const float4*)W0)[(4 * q + i) * 4 + g]);

    int qid0 = (blockIdx.x * blockDim.x + tid) >> 2;

    float S[4] = {0.f, 0.f, 0.f, 0.f};
    float Q[4] = {0.f, 0.f, 0.f, 0.f};
    const float4* eav = (const float4*)ea;
    float2* ev = (float2*)g_e;

    // ---- pipeline prologue ----
    int e0 = qid0;
    int e1 = e0 + QSTRIDE;
    int s0 = ei[e0], d0 = ei[NEDGES + e0];       // idx iter0
    int s1 = ei[e1], d1 = ei[NEDGES + e1];       // idx iter1
    float4 av0 = __ldcs(&eav[e0 * 4 + q]);       // data iter0 (streaming)
    h4 ga0 = g_h1[s0 * 4 + q];
    h4 gb0 = g_h2[d0 * 4 + q];

    #pragma unroll 1
    for (int it = 0; it < ES_ITERS; it++) {
        // stage B: data loads for iter+1 (indices arrived a full body ago)
        float4 av1;
        h4 ga1, gb1;
        if (it + 1 < ES_ITERS) {
            av1 = __ldcs(&eav[e1 * 4 + q]);
            ga1 = g_h1[s1 * 4 + q];
            gb1 = g_h2[d1 * 4 + q];
        }
        // stage A: index loads for iter+2
        int e2 = e1 + QSTRIDE, s2 = 0, d2 = 0;
        if (it + 2 < ES_ITERS) {
            s2 = ei[e2];
            d2 = ei[NEDGES + e2];
        }

        // stage C: compute current edge. acc = (ea@W0^T) quarter; gathers last.
        float acc[4] = {0.f, 0.f, 0.f, 0.f};
        #pragma unroll
        for (int g = 0; g < 4; g++) {
            int src = qbase | g;
            float x0 = __shfl_sync(0xffffffffu, av0.x, src);
            float x1 = __shfl_sync(0xffffffffu, av0.y, src);
            float x2 = __shfl_sync(0xffffffffu, av0.z, src);
            float x3 = __shfl_sync(0xffffffffu, av0.w, src);
            #pragma unroll
            for (int i = 0; i < 4; i++) {
                acc[i] = fmaf(x0, w[i][g].x, acc[i]);
                acc[i] = fmaf(x1, w[i][g].y, acc[i]);
                acc[i] = fmaf(x2, w[i][g].z, acc[i]);
                acc[i] = fmaf(x3, w[i][g].w, acc[i]);
            }
        }
        {
            float2 a01 = __half22float2(ga0.a), a23 = __half22float2(ga0.b);
            float2 b01 = __half22float2(gb0.a), b23 = __half22float2(gb0.b);
            acc[0] += a01.x + b01.x;
            acc[1] += a01.y + b01.y;
            acc[2] += a23.x + b23.x;
            acc[3] += a23.y + b23.y;
        }

        // fp32 stats (pre-rounding)
        #pragma unroll
        for (int i = 0; i < 4; i++) {
            S[i] += acc[i];
            Q[i] = fmaf(acc[i], acc[i], Q[i]);
        }
        // fp16 e to scratch (8 B/thread, lane-consecutive, streaming store)
        union { h4 h; float2 f; } hv;
        hv.h.a = __floats2half2_rn(acc[0], acc[1]);
        hv.h.b = __floats2half2_rn(acc[2], acc[3]);
        __stcs(&ev[e0 * 4 + q], hv.f);

        // rotate pipeline
        e0 = e1; av0 = av1; ga0 = ga1; gb0 = gb1;
        e1 = e2; s1 = s2; d1 = d2;
    }

    // Reduce across lanes with same q (offsets 4,8,16): lanes 0..3 hold totals
    #pragma unroll
    for (int i = 0; i < 4; i++) {
        #pragma unroll
        for (int o = 4; o < 32; o <<= 1) {
            S[i] += __shfl_xor_sync(0xffffffffu, S[i], o);
            Q[i] += __shfl_xor_sync(0xffffffffu, Q[i], o);
        }
    }
    int wrp = tid >> 5;
    if (lane < 4) {
        #pragma unroll
        for (int i = 0; i < 4; i++) {
            red[wrp][lane * 4 + i] = S[i];       // feature j = 4*lane + i
            red[wrp][16 + lane * 4 + i] = Q[i];
        }
    }
    __syncthreads();
    if (tid < 32) {
        float acc = 0.f;
        #pragma unroll
        for (int w2 = 0; w2 < 8; w2++) acc += red[w2][tid];
        atomicAdd(&g_accum[tid], acc);
    }
}

// ============================================================================
// Kernel 3: finalize BN affine
// ============================================================================
__global__ void bn_finalize(const float* __restrict__ gamma,
                            const float* __restrict__ beta) {
    int j = threadIdx.x;
    if (j < 16) {
        float inv_n = 1.0f / (float)NEDGES;
        float mean = g_accum[j] * inv_n;
        float var = g_accum[16 + j] * inv_n - mean * mean;
        float sc = gamma[j] * rsqrtf(var + 1e-5f);
        g_scale[j] = sc;
        g_shift[j] = beta[j] - mean * sc;
    }
}

// ============================================================================
// Kernel 4: pass 2 — pure streaming: out = ea + relu(e*scale + shift).
// One float4 (= one (edge, quarter) slice) per thread. At DRAM roofline.
// ============================================================================
__global__ void __launch_bounds__(256) edge_apply(const float* __restrict__ ea,
                                                  float* __restrict__ out) {
    int idx = blockIdx.x * blockDim.x + threadIdx.x;   // 0 .. NEDGES*4-1
    int q = idx & 3;
    float4 sc = ((const float4*)g_scale)[q];           // broadcast, L1-hit
    float4 sh = ((const float4*)g_shift)[q];

    float4 av = ((const float4*)ea)[idx];
    h4 v = ((const h4*)g_e)[idx];
    float2 f01 = __half22float2(v.a);
    float2 f23 = __half22float2(v.b);

    float4 o;
    o.x = av.x + fmaxf(fmaf(f01.x, sc.x, sh.x), 0.f);
    o.y = av.y + fmaxf(fmaf(f01.y, sc.y, sh.y), 0.f);
    o.z = av.z + fmaxf(fmaf(f23.x, sc.z, sh.z), 0.f);
    o.w = av.w + fmaxf(fmaf(f23.y, sc.w, sh.w), 0.f);
    ((float4*)out)[idx] = o;
}

extern "C" void kernel_launch(void* const* d_in, const int* in_sizes, int n_in,
                              void* d_out, int out_size) {
    (void)in_sizes; (void)n_in; (void)out_size;
    const float* x     = (const float*)d_in[0];
    const int*   ei    = (const int*)d_in[1];     // int32 on device (JAX x64 off)
    const float* ea    = (const float*)d_in[2];
    const float* W0    = (const float*)d_in[3];
    const float* b0    = (const float*)d_in[4];
    const float* W1    = (const float*)d_in[5];
    const float* b1    = (const float*)d_in[6];
    const float* W2    = (const float*)d_in[7];
    const float* b2    = (const float*)d_in[8];
    const float* gamma = (const float*)d_in[9];
    const float* beta  = (const float*)d_in[10];
    float* out = (float*)d_out;

    node_prep<<<(NNODES + 255) / 256, 256>>>(x, W1, W2, b0, b1, b2);
    edge_stats<<<ES_BLOCKS, ES_THREADS>>>(ea, ei, W0);  // 25 exact iters/thread
    bn_finalize<<<1, 32>>>(gamma, beta);
    edge_apply<<<(NEDGES * 4) / 256, 256>>>(ea, out);   // 50000 blocks, 1 float4/thread
}

// round 16
// speedup vs baseline: 1.1877x; 1.1877x over previous
#include <cuda_runtime.h>
#include <cuda_fp16.h>

#define NEDGES 3200000
#define NNODES 100000

// edge_stats launch geometry (compile-time so the loop is counted/predicate-free)
#define ES_BLOCKS 2000
#define ES_THREADS 256
#define QSTRIDE ((ES_BLOCKS * ES_THREADS) / 4)   // 128000 quads
#define ES_ITERS (NEDGES / QSTRIDE)              // 25 exact

struct __align__(8) h4 { __half2 a, b; };                   // 4 halves = 8 B

// Scratch (static device allocation; no cudaMalloc anywhere)
static __device__ __align__(256) h4 g_h1[NNODES * 4];       // fp16 x@W1^T + bias (6.4 MB)
static __device__ __align__(256) h4 g_h2[NNODES * 4];       // fp16 x@W2^T        (6.4 MB)
static __device__ __align__(256) __half g_e[NEDGES * 16];   // fp16 pre-BN e (102.4 MB)
static __device__ float g_accum[32];                        // sum[16], sumsq[16]
static __device__ __align__(64) float g_scale[16];
static __device__ __align__(64) float g_shift[16];

// ============================================================================
// Kernel 1: per-node precompute h1 = fp16(x@W1^T + (b0+b1+b2)), h2 = fp16(x@W2^T).
// Also zeroes the stat accumulators (stream-ordered before edge_stats).
// ============================================================================
__global__ void node_prep(const float* __restrict__ x,
                          const float* __restrict__ W1,
                          const float* __restrict__ W2,
                          const float* __restrict__ b0,
                          const float* __restrict__ b1,
                          const float* __restrict__ b2) {
    __shared__ float W1t[256], W2t[256], bt[16];
    int tid = threadIdx.x;
    {
        int j = tid >> 4, k = tid & 15;          // W[j][k] at flat idx tid
        W1t[k * 16 + j] = W1[tid];               // transpose to [k][j]
        W2t[k * 16 + j] = W2[tid];
    }
    if (tid < 16) bt[tid] = b0[tid] + b1[tid] + b2[tid];
    __syncthreads();

    int n = blockIdx.x * blockDim.x + tid;
    if (n < NNODES) {
        const float4* xv = (const float4*)x + n * 4;
        float4 x0 = xv[0], x1 = xv[1], x2 = xv[2], x3 = xv[3];
        float xr[16] = {x0.x, x0.y, x0.z, x0.w, x1.x, x1.y, x1.z, x1.w,
                        x2.x, x2.y, x2.z, x2.w, x3.x, x3.y, x3.z, x3.w};
        float a1[16], a2[16];
        #pragma unroll
        for (int j = 0; j < 16; j++) { a1[j] = bt[j]; a2[j] = 0.f; }
        #pragma unroll
        for (int k = 0; k < 16; k++) {
            float xk = xr[k];
            #pragma unroll
            for (int j = 0; j < 16; j++) {
                a1[j] = fmaf(xk, W1t[k * 16 + j], a1[j]);
                a2[j] = fmaf(xk, W2t[k * 16 + j], a2[j]);
            }
        }
        #pragma unroll
        for (int qq = 0; qq < 4; qq++) {
            h4 v1, v2;
            v1.a = __floats2half2_rn(a1[4 * qq + 0], a1[4 * qq + 1]);
            v1.b = __floats2half2_rn(a1[4 * qq + 2], a1[4 * qq + 3]);
            v2.a = __floats2half2_rn(a2[4 * qq + 0], a2[4 * qq + 1]);
            v2.b = __floats2half2_rn(a2[4 * qq + 2], a2[4 * qq + 3]);
            g_h1[n * 4 + qq] = v1;
            g_h2[n * 4 + qq] = v2;
        }
    }
    if (blockIdx.x == 0 && tid < 32) g_accum[tid] = 0.f;
}

// ============================================================================
// Kernel 2: pass 1 — quad layout (thread q owns features 4q..4q+3).
// 3-stage software pipeline: index loads 2 iterations ahead, data loads
// (ea slice + both fp16 node gathers, 1 sector each) 1 iteration ahead.
// Counted loop (25 iters exactly). W0 rows register-resident.
// Gathers combined in fp16 (__hadd2) then widened once.
// ============================================================================
__global__ void __launch_bounds__(ES_THREADS, 2) edge_stats(const float* __restrict__ ea,
                                                            const int* __restrict__ ei,
                                                            const float* __restrict__ W0) {
    __shared__ float red[8][32];
    int tid = threadIdx.x;
    int q = tid & 3;
    int lane = tid & 31;
    int qbase = lane & 28;

    // w[i][g] = W0[4q+i][4g..4g+3]  (loop-invariant, register-resident)
    float4 w[4][4];
    #pragma unroll
    for (int i = 0; i < 4; i++)
        #pragma unroll
        for (int g = 0; g < 4; g++)
            w[i][g] = __ldg(&((const float4*)W0)[(4 * q + i) * 4 + g]);

    int qid0 = (blockIdx.x * blockDim.x + tid) >> 2;

    float S[4] = {0.f, 0.f, 0.f, 0.f};
    float Q[4] = {0.f, 0.f, 0.f, 0.f};
    const float4* eav = (const float4*)ea;
    float2* ev = (float2*)g_e;

    // ---- pipeline prologue ----
    int e0 = qid0;
    int e1 = e0 + QSTRIDE;
    int s0 = ei[e0], d0 = ei[NEDGES + e0];       // idx iter0
    int s1 = ei[e1], d1 = ei[NEDGES + e1];       // idx iter1
    float4 av0 = __ldcs(&eav[e0 * 4 + q]);       // data iter0 (streaming)
    h4 ga0 = g_h1[s0 * 4 + q];
    h4 gb0 = g_h2[d0 * 4 + q];

    #pragma unroll 1
    for (int it = 0; it < ES_ITERS; it++) {
        // stage B: data loads for iter+1 (indices arrived a full body ago)
        float4 av1;
        h4 ga1, gb1;
        if (it + 1 < ES_ITERS) {
            av1 = __ldcs(&eav[e1 * 4 + q]);
            ga1 = g_h1[s1 * 4 + q];
            gb1 = g_h2[d1 * 4 + q];
        }
        // stage A: index loads for iter+2
        int e2 = e1 + QSTRIDE, s2 = 0, d2 = 0;
        if (it + 2 < ES_ITERS) {
            s2 = ei[e2];
            d2 = ei[NEDGES + e2];
        }

        // stage C: compute current edge. acc = (ea@W0^T) quarter; gathers last.
        float acc[4] = {0.f, 0.f, 0.f, 0.f};
        #pragma unroll
        for (int g = 0; g < 4; g++) {
            int src = qbase | g;
            float x0 = __shfl_sync(0xffffffffu, av0.x, src);
            float x1 = __shfl_sync(0xffffffffu, av0.y, src);
            float x2 = __shfl_sync(0xffffffffu, av0.z, src);
            float x3 = __shfl_sync(0xffffffffu, av0.w, src);
            #pragma unroll
            for (int i = 0; i < 4; i++) {
                acc[i] = fmaf(x0, w[i][g].x, acc[i]);
                acc[i] = fmaf(x1, w[i][g].y, acc[i]);
                acc[i] = fmaf(x2, w[i][g].z, acc[i]);
                acc[i] = fmaf(x3, w[i][g].w, acc[i]);
            }
        }
        {
            // combine gathers in fp16, widen once (2 HADD2 + 2 CVT + 4 FADD)
            __half2 h01 = __hadd2(ga0.a, gb0.a);
            __half2 h23 = __hadd2(ga0.b, gb0.b);
            float2 f01 = __half22float2(h01);
            float2 f23 = __half22float2(h23);
            acc[0] += f01.x;
            acc[1] += f01.y;
            acc[2] += f23.x;
            acc[3] += f23.y;
        }

        // fp32 stats (pre-rounding)
        #pragma unroll
        for (int i = 0; i < 4; i++) {
            S[i] += acc[i];
            Q[i] = fmaf(acc[i], acc[i], Q[i]);
        }
        // fp16 e to scratch (8 B/thread, lane-consecutive, streaming store)
        union { h4 h; float2 f; } hv;
        hv.h.a = __floats2half2_rn(acc[0], acc[1]);
        hv.h.b = __floats2half2_rn(acc[2], acc[3]);
        __stcs(&ev[e0 * 4 + q], hv.f);

        // rotate pipeline
        e0 = e1; av0 = av1; ga0 = ga1; gb0 = gb1;
        e1 = e2; s1 = s2; d1 = d2;
    }

    // Reduce across lanes with same q (offsets 4,8,16): lanes 0..3 hold totals
    #pragma unroll
    for (int i = 0; i < 4; i++) {
        #pragma unroll
        for (int o = 4; o < 32; o <<= 1) {
            S[i] += __shfl_xor_sync(0xffffffffu, S[i], o);
            Q[i] += __shfl_xor_sync(0xffffffffu, Q[i], o);
        }
    }
    int wrp = tid >> 5;
    if (lane < 4) {
        #pragma unroll
        for (int i = 0; i < 4; i++) {
            red[wrp][lane * 4 + i] = S[i];       // feature j = 4*lane + i
            red[wrp][16 + lane * 4 + i] = Q[i];
        }
    }
    __syncthreads();
    if (tid < 32) {
        float acc = 0.f;
        #pragma unroll
        for (int w2 = 0; w2 < 8; w2++) acc += red[w2][tid];
        atomicAdd(&g_accum[tid], acc);
    }
}

// ============================================================================
// Kernel 3: finalize BN affine
// ============================================================================
__global__ void bn_finalize(const float* __restrict__ gamma,
                            const float* __restrict__ beta) {
    int j = threadIdx.x;
    if (j < 16) {
        float inv_n = 1.0f / (float)NEDGES;
        float mean = g_accum[j] * inv_n;
        float var = g_accum[16 + j] * inv_n - mean * mean;
        float sc = gamma[j] * rsqrtf(var + 1e-5f);
        g_scale[j] = sc;
        g_shift[j] = beta[j] - mean * sc;
    }
}

// ============================================================================
// Kernel 4: pass 2 — pure streaming: out = ea + relu(e*scale + shift).
// One float4 (= one (edge, quarter) slice) per thread. At DRAM roofline.
// Also the clock-variance control: code and data identical across rounds.
// ============================================================================
__global__ void __launch_bounds__(256) edge_apply(const float* __restrict__ ea,
                                                  float* __restrict__ out) {
    int idx = blockIdx.x * blockDim.x + threadIdx.x;   // 0 .. NEDGES*4-1
    int q = idx & 3;
    float4 sc = ((const float4*)g_scale)[q];           // broadcast, L1-hit
    float4 sh = ((const float4*)g_shift)[q];

    float4 av = ((const float4*)ea)[idx];
    h4 v = ((const h4*)g_e)[idx];
    float2 f01 = __half22float2(v.a);
    float2 f23 = __half22float2(v.b);

    float4 o;
    o.x = av.x + fmaxf(fmaf(f01.x, sc.x, sh.x), 0.f);
    o.y = av.y + fmaxf(fmaf(f01.y, sc.y, sh.y), 0.f);
    o.z = av.z + fmaxf(fmaf(f23.x, sc.z, sh.z), 0.f);
    o.w = av.w + fmaxf(fmaf(f23.y, sc.w, sh.w), 0.f);
    ((float4*)out)[idx] = o;
}

extern "C" void kernel_launch(void* const* d_in, const int* in_sizes, int n_in,
                              void* d_out, int out_size) {
    (void)in_sizes; (void)n_in; (void)out_size;
    const float* x     = (const float*)d_in[0];
    const int*   ei    = (const int*)d_in[1];     // int32 on device (JAX x64 off)
    const float* ea    = (const float*)d_in[2];
    const float* W0    = (const float*)d_in[3];
    const float* b0    = (const float*)d_in[4];
    const float* W1    = (const float*)d_in[5];
    const float* b1    = (const float*)d_in[6];
    const float* W2    = (const float*)d_in[7];
    const float* b2    = (const float*)d_in[8];
    const float* gamma = (const float*)d_in[9];
    const float* beta  = (const float*)d_in[10];
    float* out = (float*)d_out;

    node_prep<<<(NNODES + 255) / 256, 256>>>(x, W1, W2, b0, b1, b2);
    edge_stats<<<ES_BLOCKS, ES_THREADS>>>(ea, ei, W0);  // 25 exact iters/thread
    bn_finalize<<<1, 32>>>(gamma, beta);
    edge_apply<<<(NEDGES * 4) / 256, 256>>>(ea, out);   // 50000 blocks, 1 float4/thread
}